// round 11
// baseline (speedup 1.0000x reference)
#include <cuda_runtime.h>
#include <cuda_fp16.h>
#include <cstdint>

// ---------------------------------------------------------------------------
// QuantizedLinear: out[8192,11008] = x[8192,4096] @ W^T
// sm_103 (non-'a' => no tcgen05). mma.sync HMMA fp16 in / fp32 accum.
//   Pass 1 (merged): x fp32 -> fp16 scratch  +  dequant w -> fp16 scratch
//   Pass 2: 128x128x32 GEMM, 128 threads, 64x64 warp tiles, 5-stage
//           cp.async (deep lookahead), 2 CTAs/SM, dbl-buffered frags,
//           pm-fastest mapping (A array L2-persistent).
// ---------------------------------------------------------------------------

#define M_TOTAL   8192
#define N_TOTAL   11008
#define K_TOTAL   4096
#define BM        128
#define BN        128
#define BK        32
#define NKT       (K_TOTAL / BK)        // 128
#define M_TILES   (M_TOTAL / BM)        // 64
#define N_TILES   (N_TOTAL / BN)        // 86

#define ROW_BYTES    80                 // 32 fp16 (64B) + 16B pad
#define A_TILE_BYTES (BM * ROW_BYTES)   // 10240
#define B_TILE_BYTES (BN * ROW_BYTES)   // 10240
#define STAGE_BYTES  (A_TILE_BYTES + B_TILE_BYTES)  // 20480
#define STAGES       5
#define SMEM_BYTES   (STAGES * STAGE_BYTES)         // 102400 (x2 CTA = 200KB)

#define CONV_BLOCKS  16384
#define DEQ_BLOCKS   11008

__device__ __align__(16) __half g_x16[(size_t)M_TOTAL * K_TOTAL];
__device__ __align__(16) __half g_w16[(size_t)N_TOTAL * K_TOTAL];

__device__ __forceinline__ uint32_t pack2(float a, float b) {
    __half2 h = __floats2half2_rn(a, b);
    return *reinterpret_cast<uint32_t*>(&h);
}

// ---------------------------------------------------------------------------
__global__ void k_prep(const float* __restrict__ x,
                       const int* __restrict__ q,
                       const float* __restrict__ scales,
                       const float* __restrict__ zeros) {
    if (blockIdx.x < CONV_BLOCKS) {
        unsigned idx = blockIdx.x * blockDim.x + threadIdx.x;
        size_t e = (size_t)idx * 8;
        const float4* src = reinterpret_cast<const float4*>(x + e);
        float4 a = src[0];
        float4 b = src[1];
        uint4 u;
        u.x = pack2(a.x, a.y);
        u.y = pack2(a.z, a.w);
        u.z = pack2(b.x, b.y);
        u.w = pack2(b.z, b.w);
        reinterpret_cast<uint4*>(g_x16)[idx] = u;
    } else {
        unsigned idx = (blockIdx.x - CONV_BLOCKS) * blockDim.x + threadIdx.x;
        unsigned o  = idx >> 8;
        unsigned k0 = (idx & 255u) * 16u;
        unsigned g  = k0 >> 7;
        float sc = scales[o * 32u + g];
        float zp = zeros [o * 32u + g];
        const int4* src = reinterpret_cast<const int4*>(q + (size_t)o * 4096 + k0);
        uint32_t outw[8];
#pragma unroll
        for (int w = 0; w < 4; w++) {
            int4 v = src[w];
            float f0 = ((float)v.x - zp) * sc;
            float f1 = ((float)v.y - zp) * sc;
            float f2 = ((float)v.z - zp) * sc;
            float f3 = ((float)v.w - zp) * sc;
            outw[w * 2]     = pack2(f0, f1);
            outw[w * 2 + 1] = pack2(f2, f3);
        }
        __half* dst = g_w16 + (size_t)o * 4096 + k0;
        reinterpret_cast<uint4*>(dst)[0] = make_uint4(outw[0], outw[1], outw[2], outw[3]);
        reinterpret_cast<uint4*>(dst)[1] = make_uint4(outw[4], outw[5], outw[6], outw[7]);
    }
}

// ---------------------------------------------------------------------------
__device__ __forceinline__ uint32_t smem_u32(const void* p) {
    return (uint32_t)__cvta_generic_to_shared(p);
}

__device__ __forceinline__ void cp_async16(uint32_t dst, const void* src) {
    asm volatile("cp.async.cg.shared.global [%0], [%1], 16;"
                 :: "r"(dst), "l"(src) : "memory");
}

__device__ __forceinline__ void ldmatrix_x4(uint32_t* r, uint32_t addr) {
    asm volatile("ldmatrix.sync.aligned.m8n8.x4.shared.b16 {%0,%1,%2,%3}, [%4];"
                 : "=r"(r[0]), "=r"(r[1]), "=r"(r[2]), "=r"(r[3]) : "r"(addr));
}

__device__ __forceinline__ void mma16816(float* c, const uint32_t* a,
                                         const uint32_t* b) {
    asm volatile(
        "mma.sync.aligned.m16n8k16.row.col.f32.f16.f16.f32 "
        "{%0,%1,%2,%3}, {%4,%5,%6,%7}, {%8,%9}, {%0,%1,%2,%3};"
        : "+f"(c[0]), "+f"(c[1]), "+f"(c[2]), "+f"(c[3])
        : "r"(a[0]), "r"(a[1]), "r"(a[2]), "r"(a[3]), "r"(b[0]), "r"(b[1]));
}

__global__ void __launch_bounds__(128, 2) k_gemm(float* __restrict__ out) {
    extern __shared__ __align__(16) unsigned char smem[];
    const uint32_t sbase = smem_u32(smem);
    const int tid  = threadIdx.x;
    const int lane = tid & 31;
    const int wid  = tid >> 5;
    const int wm   = wid >> 1;   // 0..1, 64 rows
    const int wn   = wid & 1;    // 0..1, 64 cols

    // pm-fastest mapping: each wave covers all 64 m-tiles -> A L2-persistent
    const int pm = blockIdx.x & (M_TILES - 1);
    const int pn = blockIdx.x >> 6;
    const int mbase = pm * BM;
    const int nbase = pn * BN;

    const __half* gA = g_x16 + (size_t)mbase * K_TOTAL;
    const __half* gB = g_w16 + (size_t)nbase * K_TOTAL;

    const int ar = tid >> 2;          // 0..31
    const int ac = tid & 3;           // 16B chunk 0..3
    auto load_stage = [&](int s, int kt) {
        uint32_t dst = sbase + s * STAGE_BYTES;
        const __half* srcA = gA + kt * BK;
        const __half* srcB = gB + kt * BK;
#pragma unroll
        for (int i = 0; i < 4; i++) {
            int r = ar + i * 32;
            cp_async16(dst + r * ROW_BYTES + ac * 16,
                       srcA + (size_t)r * K_TOTAL + ac * 8);
        }
#pragma unroll
        for (int i = 0; i < 4; i++) {
            int r = ar + i * 32;
            cp_async16(dst + A_TILE_BYTES + r * ROW_BYTES + ac * 16,
                       srcB + (size_t)r * K_TOTAL + ac * 8);
        }
    };

    float acc[4][8][4];
#pragma unroll
    for (int i = 0; i < 4; i++)
#pragma unroll
        for (int j = 0; j < 8; j++)
#pragma unroll
            for (int v = 0; v < 4; v++) acc[i][j][v] = 0.0f;

#pragma unroll
    for (int s = 0; s < STAGES - 1; s++) {
        load_stage(s, s);
        asm volatile("cp.async.commit_group;" ::: "memory");
    }

    const int a_row  = wm * 64 + (lane & 15);
    const int a_col8 = (lane >> 4);
    const int b_row  = wn * 64 + (lane & 7) + ((lane >> 4) << 3);
    const int b_col8 = ((lane >> 3) & 1);

    uint32_t afr[2][4][4];
    uint32_t bfr[2][8][2];

    int s = 0, sl = STAGES - 1;
    for (int kt = 0; kt < NKT; kt++) {
        asm volatile("cp.async.wait_group %0;" :: "n"(STAGES - 2) : "memory");
        __syncthreads();

        uint32_t Ab = sbase + s * STAGE_BYTES;
        uint32_t Bb = Ab + A_TILE_BYTES;

        // frags for ks=0 into buffer 0 (start the dependent chain early)
#pragma unroll
        for (int mi = 0; mi < 4; mi++)
            ldmatrix_x4(afr[0][mi],
                        Ab + (a_row + mi * 16) * ROW_BYTES + (a_col8 * 8) * 2);
#pragma unroll
        for (int bi = 0; bi < 4; bi++) {
            uint32_t r[4];
            ldmatrix_x4(r, Bb + (b_row + bi * 16) * ROW_BYTES + (b_col8 * 8) * 2);
            bfr[0][bi * 2][0]     = r[0];
            bfr[0][bi * 2][1]     = r[1];
            bfr[0][bi * 2 + 1][0] = r[2];
            bfr[0][bi * 2 + 1][1] = r[3];
        }

        if (kt + STAGES - 1 < NKT) load_stage(sl, kt + STAGES - 1);
        asm volatile("cp.async.commit_group;" ::: "memory");

#pragma unroll
        for (int ks = 0; ks < 2; ks++) {
            const int cb = ks & 1, nb = (ks & 1) ^ 1;
            if (ks < 1) {
                int koff = 16;
#pragma unroll
                for (int mi = 0; mi < 4; mi++)
                    ldmatrix_x4(afr[nb][mi],
                                Ab + (a_row + mi * 16) * ROW_BYTES
                                   + (koff + a_col8 * 8) * 2);
#pragma unroll
                for (int bi = 0; bi < 4; bi++) {
                    uint32_t r[4];
                    ldmatrix_x4(r, Bb + (b_row + bi * 16) * ROW_BYTES
                                     + (koff + b_col8 * 8) * 2);
                    bfr[nb][bi * 2][0]     = r[0];
                    bfr[nb][bi * 2][1]     = r[1];
                    bfr[nb][bi * 2 + 1][0] = r[2];
                    bfr[nb][bi * 2 + 1][1] = r[3];
                }
            }
#pragma unroll
            for (int mi = 0; mi < 4; mi++)
#pragma unroll
                for (int ni = 0; ni < 8; ni++)
                    mma16816(acc[mi][ni], afr[cb][mi], bfr[cb][ni]);
        }

        s = (s + 1 == STAGES) ? 0 : s + 1;
        sl = (sl + 1 == STAGES) ? 0 : sl + 1;
    }

    const int erow = mbase + wm * 64 + (lane >> 2);
    const int ecol = nbase + wn * 64 + (lane & 3) * 2;
#pragma unroll
    for (int mi = 0; mi < 4; mi++) {
#pragma unroll
        for (int ni = 0; ni < 8; ni++) {
            int r0 = erow + mi * 16;
            int c  = ecol + ni * 8;
            float2 v0 = make_float2(acc[mi][ni][0], acc[mi][ni][1]);
            float2 v1 = make_float2(acc[mi][ni][2], acc[mi][ni][3]);
            *reinterpret_cast<float2*>(out + (size_t)r0 * N_TOTAL + c) = v0;
            *reinterpret_cast<float2*>(out + (size_t)(r0 + 8) * N_TOTAL + c) = v1;
        }
    }
}

// ---------------------------------------------------------------------------
extern "C" void kernel_launch(void* const* d_in, const int* in_sizes, int n_in,
                              void* d_out, int out_size) {
    (void)in_sizes; (void)n_in; (void)out_size;
    const float* x  = (const float*)d_in[0];
    const int*   qw = (const int*)d_in[1];
    const float* sc = (const float*)d_in[2];
    const float* zr = (const float*)d_in[3];
    float*       out = (float*)d_out;

    cudaFuncSetAttribute(k_gemm, cudaFuncAttributeMaxDynamicSharedMemorySize,
                         SMEM_BYTES);

    k_prep<<<CONV_BLOCKS + DEQ_BLOCKS, 256>>>(x, qw, sc, zr);
    k_gemm<<<M_TILES * N_TILES, 128, SMEM_BYTES>>>(out);   // 5504 CTAs
}

// round 12
// speedup vs baseline: 1.1259x; 1.1259x over previous
#include <cuda_runtime.h>
#include <cuda_fp16.h>
#include <cstdint>

// ---------------------------------------------------------------------------
// QuantizedLinear: out[8192,11008] = x[8192,4096] @ W^T
// sm_103 (non-'a' => no tcgen05). mma.sync HMMA fp16 in / fp32 accum.
//   Pass 1 (merged): x fp32 -> fp16 scratch  +  dequant w -> fp16 scratch
//   Pass 2: persistent 128x128x64 GEMM, 128 threads, 64x64 warp tiles,
//           3-stage cp.async ring continuous ACROSS tiles, 2 CTAs/SM.
// ---------------------------------------------------------------------------

#define M_TOTAL   8192
#define N_TOTAL   11008
#define K_TOTAL   4096
#define BM        128
#define BN        128
#define BK        64
#define NKT       (K_TOTAL / BK)        // 64 k-chunks per tile
#define M_TILES   (M_TOTAL / BM)        // 64
#define N_TILES   (N_TOTAL / BN)        // 86
#define NTILES    (M_TILES * N_TILES)   // 5504
#define GROUP_M   8
#define GRID_CTAS 296                   // 2 per SM x 148 SMs

#define ROW_BYTES    144                // 64 fp16 (128B) + 16B pad
#define A_TILE_BYTES (BM * ROW_BYTES)   // 18432
#define B_TILE_BYTES (BN * ROW_BYTES)   // 18432
#define STAGE_BYTES  (A_TILE_BYTES + B_TILE_BYTES)  // 36864
#define STAGES       3
#define SMEM_BYTES   (STAGES * STAGE_BYTES)         // 110592 (x2 CTA = 221KB)

#define CONV_BLOCKS  16384
#define DEQ_BLOCKS   11008

__device__ __align__(16) __half g_x16[(size_t)M_TOTAL * K_TOTAL];
__device__ __align__(16) __half g_w16[(size_t)N_TOTAL * K_TOTAL];

__device__ __forceinline__ uint32_t pack2(float a, float b) {
    __half2 h = __floats2half2_rn(a, b);
    return *reinterpret_cast<uint32_t*>(&h);
}

// ---------------------------------------------------------------------------
__global__ void k_prep(const float* __restrict__ x,
                       const int* __restrict__ q,
                       const float* __restrict__ scales,
                       const float* __restrict__ zeros) {
    if (blockIdx.x < CONV_BLOCKS) {
        unsigned idx = blockIdx.x * blockDim.x + threadIdx.x;
        size_t e = (size_t)idx * 8;
        const float4* src = reinterpret_cast<const float4*>(x + e);
        float4 a = src[0];
        float4 b = src[1];
        uint4 u;
        u.x = pack2(a.x, a.y);
        u.y = pack2(a.z, a.w);
        u.z = pack2(b.x, b.y);
        u.w = pack2(b.z, b.w);
        reinterpret_cast<uint4*>(g_x16)[idx] = u;
    } else {
        unsigned idx = (blockIdx.x - CONV_BLOCKS) * blockDim.x + threadIdx.x;
        unsigned o  = idx >> 8;
        unsigned k0 = (idx & 255u) * 16u;
        unsigned g  = k0 >> 7;
        float sc = scales[o * 32u + g];
        float zp = zeros [o * 32u + g];
        const int4* src = reinterpret_cast<const int4*>(q + (size_t)o * 4096 + k0);
        uint32_t outw[8];
#pragma unroll
        for (int w = 0; w < 4; w++) {
            int4 v = src[w];
            float f0 = ((float)v.x - zp) * sc;
            float f1 = ((float)v.y - zp) * sc;
            float f2 = ((float)v.z - zp) * sc;
            float f3 = ((float)v.w - zp) * sc;
            outw[w * 2]     = pack2(f0, f1);
            outw[w * 2 + 1] = pack2(f2, f3);
        }
        __half* dst = g_w16 + (size_t)o * 4096 + k0;
        reinterpret_cast<uint4*>(dst)[0] = make_uint4(outw[0], outw[1], outw[2], outw[3]);
        reinterpret_cast<uint4*>(dst)[1] = make_uint4(outw[4], outw[5], outw[6], outw[7]);
    }
}

// ---------------------------------------------------------------------------
__device__ __forceinline__ uint32_t smem_u32(const void* p) {
    return (uint32_t)__cvta_generic_to_shared(p);
}

__device__ __forceinline__ void cp_async16(uint32_t dst, const void* src) {
    asm volatile("cp.async.cg.shared.global [%0], [%1], 16;"
                 :: "r"(dst), "l"(src) : "memory");
}

__device__ __forceinline__ void ldmatrix_x4(uint32_t* r, uint32_t addr) {
    asm volatile("ldmatrix.sync.aligned.m8n8.x4.shared.b16 {%0,%1,%2,%3}, [%4];"
                 : "=r"(r[0]), "=r"(r[1]), "=r"(r[2]), "=r"(r[3]) : "r"(addr));
}

__device__ __forceinline__ void mma16816(float* c, const uint32_t* a,
                                         const uint32_t* b) {
    asm volatile(
        "mma.sync.aligned.m16n8k16.row.col.f32.f16.f16.f32 "
        "{%0,%1,%2,%3}, {%4,%5,%6,%7}, {%8,%9}, {%0,%1,%2,%3};"
        : "+f"(c[0]), "+f"(c[1]), "+f"(c[2]), "+f"(c[3])
        : "r"(a[0]), "r"(a[1]), "r"(a[2]), "r"(a[3]), "r"(b[0]), "r"(b[1]));
}

// tile id -> (mbase, nbase) with GROUP_M grouping
__device__ __forceinline__ void tile_coords(int t, int& mbase, int& nbase) {
    int grp  = t / (GROUP_M * N_TILES);
    int inpg = t % (GROUP_M * N_TILES);
    int pm   = grp * GROUP_M + (inpg % GROUP_M);
    int pn   = inpg / GROUP_M;
    mbase = pm * BM;
    nbase = pn * BN;
}

__global__ void __launch_bounds__(128, 2) k_gemm(float* __restrict__ out) {
    extern __shared__ __align__(16) unsigned char smem[];
    const uint32_t sbase = smem_u32(smem);
    const int tid  = threadIdx.x;
    const int lane = tid & 31;
    const int wid  = tid >> 5;
    const int wm   = wid >> 1;   // 0..1, 64 rows
    const int wn   = wid & 1;    // 0..1, 64 cols
    const int bid  = blockIdx.x;

    const int ntiles  = (NTILES - bid + GRID_CTAS - 1) / GRID_CTAS;
    const int total_f = ntiles * NKT;

    const int ar = tid >> 3;          // 0..15
    const int ac = tid & 7;           // 16B chunk 0..7
    auto load_stage = [&](int s, int kt, const __half* gA, const __half* gB) {
        uint32_t dst = sbase + s * STAGE_BYTES;
        const __half* srcA = gA + kt * BK;
        const __half* srcB = gB + kt * BK;
#pragma unroll
        for (int i = 0; i < 8; i++) {
            int r = ar + i * 16;
            cp_async16(dst + r * ROW_BYTES + ac * 16,
                       srcA + (size_t)r * K_TOTAL + ac * 8);
        }
#pragma unroll
        for (int i = 0; i < 8; i++) {
            int r = ar + i * 16;
            cp_async16(dst + A_TILE_BYTES + r * ROW_BYTES + ac * 16,
                       srcB + (size_t)r * K_TOTAL + ac * 8);
        }
    };

    // compute-side tile cursor
    int ctile = bid;
    int mbase, nbase;
    tile_coords(ctile, mbase, nbase);

    // load-side tile cursor (tile of flat index f+2; starts at tile 0)
    int mbl, nbl;
    tile_coords(bid, mbl, nbl);
    const __half* gAl = g_x16 + (size_t)mbl * K_TOTAL;
    const __half* gBl = g_w16 + (size_t)nbl * K_TOTAL;
    int ltile_i = 0;   // which of this CTA's tiles the load cursor is on

    float acc[4][8][4];
#pragma unroll
    for (int i = 0; i < 4; i++)
#pragma unroll
        for (int j = 0; j < 8; j++)
#pragma unroll
            for (int v = 0; v < 4; v++) acc[i][j][v] = 0.0f;

    // prologue: flat 0 and 1 (kt 0,1 of this CTA's first tile)
    load_stage(0, 0, gAl, gBl);
    asm volatile("cp.async.commit_group;" ::: "memory");
    load_stage(1, 1, gAl, gBl);
    asm volatile("cp.async.commit_group;" ::: "memory");

    const int a_row  = wm * 64 + (lane & 15);
    const int a_col8 = (lane >> 4);
    const int b_row  = wn * 64 + (lane & 7) + ((lane >> 4) << 3);
    const int b_col8 = ((lane >> 3) & 1);

    uint32_t afr[2][4][4];
    uint32_t bfr[2][8][2];

    int s = 0, sl = STAGES - 1;
    for (int f = 0; f < total_f; f++) {
        const int kt = f & (NKT - 1);

        asm volatile("cp.async.wait_group %0;" :: "n"(STAGES - 2) : "memory");
        __syncthreads();

        uint32_t Ab = sbase + s * STAGE_BYTES;
        uint32_t Bb = Ab + A_TILE_BYTES;

        // frags for ks=0 into buffer 0
#pragma unroll
        for (int mi = 0; mi < 4; mi++)
            ldmatrix_x4(afr[0][mi],
                        Ab + (a_row + mi * 16) * ROW_BYTES + (a_col8 * 8) * 2);
#pragma unroll
        for (int bi = 0; bi < 4; bi++) {
            uint32_t r[4];
            ldmatrix_x4(r, Bb + (b_row + bi * 16) * ROW_BYTES + (b_col8 * 8) * 2);
            bfr[0][bi * 2][0]     = r[0];
            bfr[0][bi * 2][1]     = r[1];
            bfr[0][bi * 2 + 1][0] = r[2];
            bfr[0][bi * 2 + 1][1] = r[3];
        }

        // loads for flat f+2 (may belong to the next tile -> ring continues)
        const int fl = f + 2;
        if (fl < total_f) {
            const int li = fl >> 6;              // tile ordinal for load side
            if (li != ltile_i) {
                ltile_i = li;
                tile_coords(bid + li * GRID_CTAS, mbl, nbl);
                gAl = g_x16 + (size_t)mbl * K_TOTAL;
                gBl = g_w16 + (size_t)nbl * K_TOTAL;
            }
            load_stage(sl, fl & (NKT - 1), gAl, gBl);
        }
        asm volatile("cp.async.commit_group;" ::: "memory");

#pragma unroll
        for (int ks = 0; ks < 4; ks++) {
            const int cb = ks & 1, nb = (ks & 1) ^ 1;
            if (ks < 3) {
                int koff = (ks + 1) * 16;
#pragma unroll
                for (int mi = 0; mi < 4; mi++)
                    ldmatrix_x4(afr[nb][mi],
                                Ab + (a_row + mi * 16) * ROW_BYTES
                                   + (koff + a_col8 * 8) * 2);
#pragma unroll
                for (int bi = 0; bi < 4; bi++) {
                    uint32_t r[4];
                    ldmatrix_x4(r, Bb + (b_row + bi * 16) * ROW_BYTES
                                     + (koff + b_col8 * 8) * 2);
                    bfr[nb][bi * 2][0]     = r[0];
                    bfr[nb][bi * 2][1]     = r[1];
                    bfr[nb][bi * 2 + 1][0] = r[2];
                    bfr[nb][bi * 2 + 1][1] = r[3];
                }
            }
#pragma unroll
            for (int mi = 0; mi < 4; mi++)
#pragma unroll
                for (int ni = 0; ni < 8; ni++)
                    mma16816(acc[mi][ni], afr[cb][mi], bfr[cb][ni]);
        }

        if (kt == NKT - 1) {
            // epilogue for ctile (register-only source; overlaps in-flight loads)
            const int erow = mbase + wm * 64 + (lane >> 2);
            const int ecol = nbase + wn * 64 + (lane & 3) * 2;
#pragma unroll
            for (int mi = 0; mi < 4; mi++) {
#pragma unroll
                for (int ni = 0; ni < 8; ni++) {
                    int r0 = erow + mi * 16;
                    int c  = ecol + ni * 8;
                    float2 v0 = make_float2(acc[mi][ni][0], acc[mi][ni][1]);
                    float2 v1 = make_float2(acc[mi][ni][2], acc[mi][ni][3]);
                    *reinterpret_cast<float2*>(out + (size_t)r0 * N_TOTAL + c) = v0;
                    *reinterpret_cast<float2*>(out + (size_t)(r0 + 8) * N_TOTAL + c) = v1;
                    acc[mi][ni][0] = 0.0f;
                    acc[mi][ni][1] = 0.0f;
                    acc[mi][ni][2] = 0.0f;
                    acc[mi][ni][3] = 0.0f;
                }
            }
            if (f + 1 < total_f) {
                ctile += GRID_CTAS;
                tile_coords(ctile, mbase, nbase);
            }
        }

        s = (s + 1 == STAGES) ? 0 : s + 1;
        sl = (sl + 1 == STAGES) ? 0 : sl + 1;
    }
}

// ---------------------------------------------------------------------------
extern "C" void kernel_launch(void* const* d_in, const int* in_sizes, int n_in,
                              void* d_out, int out_size) {
    (void)in_sizes; (void)n_in; (void)out_size;
    const float* x  = (const float*)d_in[0];
    const int*   qw = (const int*)d_in[1];
    const float* sc = (const float*)d_in[2];
    const float* zr = (const float*)d_in[3];
    float*       out = (float*)d_out;

    cudaFuncSetAttribute(k_gemm, cudaFuncAttributeMaxDynamicSharedMemorySize,
                         SMEM_BYTES);

    k_prep<<<CONV_BLOCKS + DEQ_BLOCKS, 256>>>(x, qw, sc, zr);
    k_gemm<<<GRID_CTAS, 128, SMEM_BYTES>>>(out);   // persistent, 2 CTAs/SM
}

// round 13
// speedup vs baseline: 1.2407x; 1.1020x over previous
#include <cuda_runtime.h>
#include <cuda_fp16.h>
#include <cstdint>

// ---------------------------------------------------------------------------
// QuantizedLinear: out[8192,11008] = x[8192,4096] @ W^T
// sm_103 (non-'a' => no tcgen05). mma.sync HMMA fp16 in / fp32 accum.
//   Pass 1 (merged): x fp32 -> fp16 scratch  +  dequant w -> fp16 scratch
//   Pass 2: 128x128x64 GEMM, 128 threads, 64x64 warp tiles, 3-stage
//           cp.async, 2 CTAs/SM, dbl-buffered frags; cp.async burst issued
//           AFTER the ks=0 mma block (LSU clear at the frag-chain head).
// ---------------------------------------------------------------------------

#define M_TOTAL   8192
#define N_TOTAL   11008
#define K_TOTAL   4096
#define BM        128
#define BN        128
#define BK        64
#define NKT       (K_TOTAL / BK)        // 64
#define M_TILES   (M_TOTAL / BM)        // 64
#define N_TILES   (N_TOTAL / BN)        // 86
#define GROUP_M   8

#define ROW_BYTES    144                // 64 fp16 (128B) + 16B pad
#define A_TILE_BYTES (BM * ROW_BYTES)   // 18432
#define B_TILE_BYTES (BN * ROW_BYTES)   // 18432
#define STAGE_BYTES  (A_TILE_BYTES + B_TILE_BYTES)  // 36864
#define STAGES       3
#define SMEM_BYTES   (STAGES * STAGE_BYTES)         // 110592 (x2 CTA = 221KB)

#define CONV_BLOCKS  16384
#define DEQ_BLOCKS   11008

__device__ __align__(16) __half g_x16[(size_t)M_TOTAL * K_TOTAL];
__device__ __align__(16) __half g_w16[(size_t)N_TOTAL * K_TOTAL];

__device__ __forceinline__ uint32_t pack2(float a, float b) {
    __half2 h = __floats2half2_rn(a, b);
    return *reinterpret_cast<uint32_t*>(&h);
}

// ---------------------------------------------------------------------------
__global__ void k_prep(const float* __restrict__ x,
                       const int* __restrict__ q,
                       const float* __restrict__ scales,
                       const float* __restrict__ zeros) {
    if (blockIdx.x < CONV_BLOCKS) {
        unsigned idx = blockIdx.x * blockDim.x + threadIdx.x;
        size_t e = (size_t)idx * 8;
        const float4* src = reinterpret_cast<const float4*>(x + e);
        float4 a = src[0];
        float4 b = src[1];
        uint4 u;
        u.x = pack2(a.x, a.y);
        u.y = pack2(a.z, a.w);
        u.z = pack2(b.x, b.y);
        u.w = pack2(b.z, b.w);
        reinterpret_cast<uint4*>(g_x16)[idx] = u;
    } else {
        unsigned idx = (blockIdx.x - CONV_BLOCKS) * blockDim.x + threadIdx.x;
        unsigned o  = idx >> 8;
        unsigned k0 = (idx & 255u) * 16u;
        unsigned g  = k0 >> 7;
        float sc = scales[o * 32u + g];
        float zp = zeros [o * 32u + g];
        const int4* src = reinterpret_cast<const int4*>(q + (size_t)o * 4096 + k0);
        uint32_t outw[8];
#pragma unroll
        for (int w = 0; w < 4; w++) {
            int4 v = src[w];
            float f0 = ((float)v.x - zp) * sc;
            float f1 = ((float)v.y - zp) * sc;
            float f2 = ((float)v.z - zp) * sc;
            float f3 = ((float)v.w - zp) * sc;
            outw[w * 2]     = pack2(f0, f1);
            outw[w * 2 + 1] = pack2(f2, f3);
        }
        __half* dst = g_w16 + (size_t)o * 4096 + k0;
        reinterpret_cast<uint4*>(dst)[0] = make_uint4(outw[0], outw[1], outw[2], outw[3]);
        reinterpret_cast<uint4*>(dst)[1] = make_uint4(outw[4], outw[5], outw[6], outw[7]);
    }
}

// ---------------------------------------------------------------------------
__device__ __forceinline__ uint32_t smem_u32(const void* p) {
    return (uint32_t)__cvta_generic_to_shared(p);
}

__device__ __forceinline__ void cp_async16(uint32_t dst, const void* src) {
    asm volatile("cp.async.cg.shared.global [%0], [%1], 16;"
                 :: "r"(dst), "l"(src) : "memory");
}

__device__ __forceinline__ void ldmatrix_x4(uint32_t* r, uint32_t addr) {
    asm volatile("ldmatrix.sync.aligned.m8n8.x4.shared.b16 {%0,%1,%2,%3}, [%4];"
                 : "=r"(r[0]), "=r"(r[1]), "=r"(r[2]), "=r"(r[3]) : "r"(addr));
}

__device__ __forceinline__ void mma16816(float* c, const uint32_t* a,
                                         const uint32_t* b) {
    asm volatile(
        "mma.sync.aligned.m16n8k16.row.col.f32.f16.f16.f32 "
        "{%0,%1,%2,%3}, {%4,%5,%6,%7}, {%8,%9}, {%0,%1,%2,%3};"
        : "+f"(c[0]), "+f"(c[1]), "+f"(c[2]), "+f"(c[3])
        : "r"(a[0]), "r"(a[1]), "r"(a[2]), "r"(a[3]), "r"(b[0]), "r"(b[1]));
}

__global__ void __launch_bounds__(128, 2) k_gemm(float* __restrict__ out) {
    extern __shared__ __align__(16) unsigned char smem[];
    const uint32_t sbase = smem_u32(smem);
    const int tid  = threadIdx.x;
    const int lane = tid & 31;
    const int wid  = tid >> 5;
    const int wm   = wid >> 1;   // 0..1, 64 rows
    const int wn   = wid & 1;    // 0..1, 64 cols

    int pid   = blockIdx.x;
    int grp   = pid / (GROUP_M * N_TILES);
    int inpg  = pid % (GROUP_M * N_TILES);
    int pm    = grp * GROUP_M + (inpg % GROUP_M);
    int pn    = inpg / GROUP_M;
    const int mbase = pm * BM;
    const int nbase = pn * BN;

    const __half* gA = g_x16 + (size_t)mbase * K_TOTAL;
    const __half* gB = g_w16 + (size_t)nbase * K_TOTAL;

    const int ar = tid >> 3;          // 0..15
    const int ac = tid & 7;           // 16B chunk 0..7
    auto load_stage = [&](int s, int kt) {
        uint32_t dst = sbase + s * STAGE_BYTES;
        const __half* srcA = gA + kt * BK;
        const __half* srcB = gB + kt * BK;
#pragma unroll
        for (int i = 0; i < 8; i++) {
            int r = ar + i * 16;
            cp_async16(dst + r * ROW_BYTES + ac * 16,
                       srcA + (size_t)r * K_TOTAL + ac * 8);
        }
#pragma unroll
        for (int i = 0; i < 8; i++) {
            int r = ar + i * 16;
            cp_async16(dst + A_TILE_BYTES + r * ROW_BYTES + ac * 16,
                       srcB + (size_t)r * K_TOTAL + ac * 8);
        }
    };

    float acc[4][8][4];
#pragma unroll
    for (int i = 0; i < 4; i++)
#pragma unroll
        for (int j = 0; j < 8; j++)
#pragma unroll
            for (int v = 0; v < 4; v++) acc[i][j][v] = 0.0f;

#pragma unroll
    for (int s = 0; s < STAGES - 1; s++) {
        load_stage(s, s);
        asm volatile("cp.async.commit_group;" ::: "memory");
    }

    const int a_row  = wm * 64 + (lane & 15);
    const int a_col8 = (lane >> 4);
    const int b_row  = wn * 64 + (lane & 7) + ((lane >> 4) << 3);
    const int b_col8 = ((lane >> 3) & 1);

    uint32_t afr[2][4][4];
    uint32_t bfr[2][8][2];

    int s = 0, sl = STAGES - 1;
    for (int kt = 0; kt < NKT; kt++) {
        asm volatile("cp.async.wait_group %0;" :: "n"(STAGES - 2) : "memory");
        __syncthreads();

        uint32_t Ab = sbase + s * STAGE_BYTES;
        uint32_t Bb = Ab + A_TILE_BYTES;

        // frags for ks=0 into buffer 0
#pragma unroll
        for (int mi = 0; mi < 4; mi++)
            ldmatrix_x4(afr[0][mi],
                        Ab + (a_row + mi * 16) * ROW_BYTES + (a_col8 * 8) * 2);
#pragma unroll
        for (int bi = 0; bi < 4; bi++) {
            uint32_t r[4];
            ldmatrix_x4(r, Bb + (b_row + bi * 16) * ROW_BYTES + (b_col8 * 8) * 2);
            bfr[0][bi * 2][0]     = r[0];
            bfr[0][bi * 2][1]     = r[1];
            bfr[0][bi * 2 + 1][0] = r[2];
            bfr[0][bi * 2 + 1][1] = r[3];
        }

#pragma unroll
        for (int ks = 0; ks < 4; ks++) {
            const int cb = ks & 1, nb = (ks & 1) ^ 1;
            if (ks < 3) {
                int koff = (ks + 1) * 16;
#pragma unroll
                for (int mi = 0; mi < 4; mi++)
                    ldmatrix_x4(afr[nb][mi],
                                Ab + (a_row + mi * 16) * ROW_BYTES
                                   + (koff + a_col8 * 8) * 2);
#pragma unroll
                for (int bi = 0; bi < 4; bi++) {
                    uint32_t r[4];
                    ldmatrix_x4(r, Bb + (b_row + bi * 16) * ROW_BYTES
                                     + (koff + b_col8 * 8) * 2);
                    bfr[nb][bi * 2][0]     = r[0];
                    bfr[nb][bi * 2][1]     = r[1];
                    bfr[nb][bi * 2 + 1][0] = r[2];
                    bfr[nb][bi * 2 + 1][1] = r[3];
                }
            }
#pragma unroll
            for (int mi = 0; mi < 4; mi++)
#pragma unroll
                for (int ni = 0; ni < 8; ni++)
                    mma16816(acc[mi][ni], afr[cb][mi], bfr[cb][ni]);

            // issue the global-load burst after the ks=0 mma block:
            // LSU is clear at the kt-head frag chain; 3 more mma blocks
            // (~768 tensor-busy cycles) still cover the cp.async issue cost,
            // and the ring keeps ~2 kt of lookahead (>> L2 latency).
            if (ks == 0) {
                if (kt + STAGES - 1 < NKT) load_stage(sl, kt + STAGES - 1);
                asm volatile("cp.async.commit_group;" ::: "memory");
            }
        }

        s = (s + 1 == STAGES) ? 0 : s + 1;
        sl = (sl + 1 == STAGES) ? 0 : sl + 1;
    }

    const int erow = mbase + wm * 64 + (lane >> 2);
    const int ecol = nbase + wn * 64 + (lane & 3) * 2;
#pragma unroll
    for (int mi = 0; mi < 4; mi++) {
#pragma unroll
        for (int ni = 0; ni < 8; ni++) {
            int r0 = erow + mi * 16;
            int c  = ecol + ni * 8;
            float2 v0 = make_float2(acc[mi][ni][0], acc[mi][ni][1]);
            float2 v1 = make_float2(acc[mi][ni][2], acc[mi][ni][3]);
            *reinterpret_cast<float2*>(out + (size_t)r0 * N_TOTAL + c) = v0;
            *reinterpret_cast<float2*>(out + (size_t)(r0 + 8) * N_TOTAL + c) = v1;
        }
    }
}

// ---------------------------------------------------------------------------
extern "C" void kernel_launch(void* const* d_in, const int* in_sizes, int n_in,
                              void* d_out, int out_size) {
    (void)in_sizes; (void)n_in; (void)out_size;
    const float* x  = (const float*)d_in[0];
    const int*   qw = (const int*)d_in[1];
    const float* sc = (const float*)d_in[2];
    const float* zr = (const float*)d_in[3];
    float*       out = (float*)d_out;

    cudaFuncSetAttribute(k_gemm, cudaFuncAttributeMaxDynamicSharedMemorySize,
                         SMEM_BYTES);

    k_prep<<<CONV_BLOCKS + DEQ_BLOCKS, 256>>>(x, qw, sc, zr);
    k_gemm<<<M_TILES * N_TILES, 128, SMEM_BYTES>>>(out);   // 5504 CTAs
}

// round 14
// speedup vs baseline: 1.4710x; 1.1857x over previous
#include <cuda_runtime.h>
#include <cuda_fp16.h>
#include <cstdint>

// ---------------------------------------------------------------------------
// QuantizedLinear: out[8192,11008] = x[8192,4096] @ W^T
// sm_103 (non-'a' => no tcgen05). mma.sync HMMA fp16 in / fp32 accum.
//   Pass 1 (merged): x fp32 -> fp16 scratch  +  dequant w -> fp16 scratch
//   Pass 2: 128x128x64 GEMM, 128 threads, 64x64 warp tiles, 3-stage
//           cp.async, 2 CTAs/SM. Burst after ks0-mma (R13 win) + cross-stage
//           fragment prefetch: barrier moved between ks2 and ks3; ks3
//           prefetches next-kt ks0 frags from the already-resident stage.
// ---------------------------------------------------------------------------

#define M_TOTAL   8192
#define N_TOTAL   11008
#define K_TOTAL   4096
#define BM        128
#define BN        128
#define BK        64
#define NKT       (K_TOTAL / BK)        // 64
#define M_TILES   (M_TOTAL / BM)        // 64
#define N_TILES   (N_TOTAL / BN)        // 86
#define GROUP_M   8

#define ROW_BYTES    144                // 64 fp16 (128B) + 16B pad
#define A_TILE_BYTES (BM * ROW_BYTES)   // 18432
#define B_TILE_BYTES (BN * ROW_BYTES)   // 18432
#define STAGE_BYTES  (A_TILE_BYTES + B_TILE_BYTES)  // 36864
#define STAGES       3
#define SMEM_BYTES   (STAGES * STAGE_BYTES)         // 110592 (x2 CTA = 221KB)

#define CONV_BLOCKS  16384
#define DEQ_BLOCKS   11008

__device__ __align__(16) __half g_x16[(size_t)M_TOTAL * K_TOTAL];
__device__ __align__(16) __half g_w16[(size_t)N_TOTAL * K_TOTAL];

__device__ __forceinline__ uint32_t pack2(float a, float b) {
    __half2 h = __floats2half2_rn(a, b);
    return *reinterpret_cast<uint32_t*>(&h);
}

// ---------------------------------------------------------------------------
__global__ void k_prep(const float* __restrict__ x,
                       const int* __restrict__ q,
                       const float* __restrict__ scales,
                       const float* __restrict__ zeros) {
    if (blockIdx.x < CONV_BLOCKS) {
        unsigned idx = blockIdx.x * blockDim.x + threadIdx.x;
        size_t e = (size_t)idx * 8;
        const float4* src = reinterpret_cast<const float4*>(x + e);
        float4 a = src[0];
        float4 b = src[1];
        uint4 u;
        u.x = pack2(a.x, a.y);
        u.y = pack2(a.z, a.w);
        u.z = pack2(b.x, b.y);
        u.w = pack2(b.z, b.w);
        reinterpret_cast<uint4*>(g_x16)[idx] = u;
    } else {
        unsigned idx = (blockIdx.x - CONV_BLOCKS) * blockDim.x + threadIdx.x;
        unsigned o  = idx >> 8;
        unsigned k0 = (idx & 255u) * 16u;
        unsigned g  = k0 >> 7;
        float sc = scales[o * 32u + g];
        float zp = zeros [o * 32u + g];
        const int4* src = reinterpret_cast<const int4*>(q + (size_t)o * 4096 + k0);
        uint32_t outw[8];
#pragma unroll
        for (int w = 0; w < 4; w++) {
            int4 v = src[w];
            float f0 = ((float)v.x - zp) * sc;
            float f1 = ((float)v.y - zp) * sc;
            float f2 = ((float)v.z - zp) * sc;
            float f3 = ((float)v.w - zp) * sc;
            outw[w * 2]     = pack2(f0, f1);
            outw[w * 2 + 1] = pack2(f2, f3);
        }
        __half* dst = g_w16 + (size_t)o * 4096 + k0;
        reinterpret_cast<uint4*>(dst)[0] = make_uint4(outw[0], outw[1], outw[2], outw[3]);
        reinterpret_cast<uint4*>(dst)[1] = make_uint4(outw[4], outw[5], outw[6], outw[7]);
    }
}

// ---------------------------------------------------------------------------
__device__ __forceinline__ uint32_t smem_u32(const void* p) {
    return (uint32_t)__cvta_generic_to_shared(p);
}

__device__ __forceinline__ void cp_async16(uint32_t dst, const void* src) {
    asm volatile("cp.async.cg.shared.global [%0], [%1], 16;"
                 :: "r"(dst), "l"(src) : "memory");
}

__device__ __forceinline__ void ldmatrix_x4(uint32_t* r, uint32_t addr) {
    asm volatile("ldmatrix.sync.aligned.m8n8.x4.shared.b16 {%0,%1,%2,%3}, [%4];"
                 : "=r"(r[0]), "=r"(r[1]), "=r"(r[2]), "=r"(r[3]) : "r"(addr));
}

__device__ __forceinline__ void mma16816(float* c, const uint32_t* a,
                                         const uint32_t* b) {
    asm volatile(
        "mma.sync.aligned.m16n8k16.row.col.f32.f16.f16.f32 "
        "{%0,%1,%2,%3}, {%4,%5,%6,%7}, {%8,%9}, {%0,%1,%2,%3};"
        : "+f"(c[0]), "+f"(c[1]), "+f"(c[2]), "+f"(c[3])
        : "r"(a[0]), "r"(a[1]), "r"(a[2]), "r"(a[3]), "r"(b[0]), "r"(b[1]));
}

__global__ void __launch_bounds__(128, 2) k_gemm(float* __restrict__ out) {
    extern __shared__ __align__(16) unsigned char smem[];
    const uint32_t sbase = smem_u32(smem);
    const int tid  = threadIdx.x;
    const int lane = tid & 31;
    const int wid  = tid >> 5;
    const int wm   = wid >> 1;   // 0..1, 64 rows
    const int wn   = wid & 1;    // 0..1, 64 cols

    int pid   = blockIdx.x;
    int grp   = pid / (GROUP_M * N_TILES);
    int inpg  = pid % (GROUP_M * N_TILES);
    int pm    = grp * GROUP_M + (inpg % GROUP_M);
    int pn    = inpg / GROUP_M;
    const int mbase = pm * BM;
    const int nbase = pn * BN;

    const __half* gA = g_x16 + (size_t)mbase * K_TOTAL;
    const __half* gB = g_w16 + (size_t)nbase * K_TOTAL;

    const int ar = tid >> 3;          // 0..15
    const int ac = tid & 7;           // 16B chunk 0..7
    auto load_stage = [&](int s, int kt) {
        uint32_t dst = sbase + s * STAGE_BYTES;
        const __half* srcA = gA + kt * BK;
        const __half* srcB = gB + kt * BK;
#pragma unroll
        for (int i = 0; i < 8; i++) {
            int r = ar + i * 16;
            cp_async16(dst + r * ROW_BYTES + ac * 16,
                       srcA + (size_t)r * K_TOTAL + ac * 8);
        }
#pragma unroll
        for (int i = 0; i < 8; i++) {
            int r = ar + i * 16;
            cp_async16(dst + A_TILE_BYTES + r * ROW_BYTES + ac * 16,
                       srcB + (size_t)r * K_TOTAL + ac * 8);
        }
    };

    float acc[4][8][4];
#pragma unroll
    for (int i = 0; i < 4; i++)
#pragma unroll
        for (int j = 0; j < 8; j++)
#pragma unroll
            for (int v = 0; v < 4; v++) acc[i][j][v] = 0.0f;

    const int a_row  = wm * 64 + (lane & 15);
    const int a_col8 = (lane >> 4);
    const int b_row  = wn * 64 + (lane & 7) + ((lane >> 4) << 3);
    const int b_col8 = ((lane >> 3) & 1);

    uint32_t afr[2][4][4];
    uint32_t bfr[2][8][2];

    // ldsm fragment loads for a given k-offset (bytes = koff*2) from Ab/Bb
    auto ldsm_frags = [&](int buf, uint32_t Ab, uint32_t Bb, int koff) {
#pragma unroll
        for (int mi = 0; mi < 4; mi++)
            ldmatrix_x4(afr[buf][mi],
                        Ab + (a_row + mi * 16) * ROW_BYTES
                           + (koff + a_col8 * 8) * 2);
#pragma unroll
        for (int bi = 0; bi < 4; bi++) {
            uint32_t r[4];
            ldmatrix_x4(r, Bb + (b_row + bi * 16) * ROW_BYTES
                             + (koff + b_col8 * 8) * 2);
            bfr[buf][bi * 2][0]     = r[0];
            bfr[buf][bi * 2][1]     = r[1];
            bfr[buf][bi * 2 + 1][0] = r[2];
            bfr[buf][bi * 2 + 1][1] = r[3];
        }
    };
    auto mma_block = [&](int buf) {
#pragma unroll
        for (int mi = 0; mi < 4; mi++)
#pragma unroll
            for (int ni = 0; ni < 8; ni++)
                mma16816(acc[mi][ni], afr[buf][mi], bfr[buf][ni]);
    };

    // prologue: fill stages 0,1
    load_stage(0, 0);
    asm volatile("cp.async.commit_group;" ::: "memory");
    load_stage(1, 1);
    asm volatile("cp.async.commit_group;" ::: "memory");
    asm volatile("cp.async.wait_group 1;" ::: "memory");
    __syncthreads();

    // ks=0 frags of kt=0 into buffer 0
    ldsm_frags(0, sbase, sbase + A_TILE_BYTES, 0);

    int s = 0, sl = STAGES - 1;
    for (int kt = 0; kt < NKT; kt++) {
        uint32_t Ab = sbase + s * STAGE_BYTES;
        uint32_t Bb = Ab + A_TILE_BYTES;
        int snext = (s + 1 == STAGES) ? 0 : s + 1;
        uint32_t AbN = sbase + snext * STAGE_BYTES;
        uint32_t BbN = AbN + A_TILE_BYTES;

        // ks = 0
        ldsm_frags(1, Ab, Bb, 16);
        mma_block(0);
        if (kt + STAGES - 1 < NKT) load_stage(sl, kt + STAGES - 1);
        asm volatile("cp.async.commit_group;" ::: "memory");

        // ks = 1
        ldsm_frags(0, Ab, Bb, 32);
        mma_block(1);

        // ks = 2
        ldsm_frags(1, Ab, Bb, 48);
        mma_block(0);

        // stage kt+1 is guaranteed complete after this wait (only the
        // kt+2 group remains pending); barrier sits where both adjacent
        // mma blocks have register-resident operands.
        asm volatile("cp.async.wait_group %0;" :: "n"(STAGES - 2) : "memory");
        __syncthreads();

        // ks = 3: prefetch next kt's ks=0 frags from the resident next stage
        if (kt + 1 < NKT) ldsm_frags(0, AbN, BbN, 0);
        mma_block(1);

        s = snext;
        sl = (sl + 1 == STAGES) ? 0 : sl + 1;
    }

    const int erow = mbase + wm * 64 + (lane >> 2);
    const int ecol = nbase + wn * 64 + (lane & 3) * 2;
#pragma unroll
    for (int mi = 0; mi < 4; mi++) {
#pragma unroll
        for (int ni = 0; ni < 8; ni++) {
            int r0 = erow + mi * 16;
            int c  = ecol + ni * 8;
            float2 v0 = make_float2(acc[mi][ni][0], acc[mi][ni][1]);
            float2 v1 = make_float2(acc[mi][ni][2], acc[mi][ni][3]);
            *reinterpret_cast<float2*>(out + (size_t)r0 * N_TOTAL + c) = v0;
            *reinterpret_cast<float2*>(out + (size_t)(r0 + 8) * N_TOTAL + c) = v1;
        }
    }
}

// ---------------------------------------------------------------------------
extern "C" void kernel_launch(void* const* d_in, const int* in_sizes, int n_in,
                              void* d_out, int out_size) {
    (void)in_sizes; (void)n_in; (void)out_size;
    const float* x  = (const float*)d_in[0];
    const int*   qw = (const int*)d_in[1];
    const float* sc = (const float*)d_in[2];
    const float* zr = (const float*)d_in[3];
    float*       out = (float*)d_out;

    cudaFuncSetAttribute(k_gemm, cudaFuncAttributeMaxDynamicSharedMemorySize,
                         SMEM_BYTES);

    k_prep<<<CONV_BLOCKS + DEQ_BLOCKS, 256>>>(x, qw, sc, zr);
    k_gemm<<<M_TILES * N_TILES, 128, SMEM_BYTES>>>(out);   // 5504 CTAs
}

// round 15
// speedup vs baseline: 1.4716x; 1.0004x over previous
#include <cuda_runtime.h>
#include <cuda_fp16.h>
#include <cstdint>

// ---------------------------------------------------------------------------
// QuantizedLinear: out[8192,11008] = x[8192,4096] @ W^T
// sm_103 (non-'a' => no tcgen05). mma.sync HMMA fp16 in / fp32 accum.
//   Pass 1 (merged): x fp32 -> fp16 scratch  +  dequant w -> fp16 scratch
//   Pass 2: 128x128x64 GEMM, 128 threads, 64x64 warp tiles, 3-stage
//           cp.async, 2 CTAs/SM. R14 schedule (cross-stage frag prefetch,
//           barrier between ks2/ks3) + split A/B load bursts (ks0/ks1) +
//           evict-first output stores.
// ---------------------------------------------------------------------------

#define M_TOTAL   8192
#define N_TOTAL   11008
#define K_TOTAL   4096
#define BM        128
#define BN        128
#define BK        64
#define NKT       (K_TOTAL / BK)        // 64
#define M_TILES   (M_TOTAL / BM)        // 64
#define N_TILES   (N_TOTAL / BN)        // 86
#define GROUP_M   8

#define ROW_BYTES    144                // 64 fp16 (128B) + 16B pad
#define A_TILE_BYTES (BM * ROW_BYTES)   // 18432
#define B_TILE_BYTES (BN * ROW_BYTES)   // 18432
#define STAGE_BYTES  (A_TILE_BYTES + B_TILE_BYTES)  // 36864
#define STAGES       3
#define SMEM_BYTES   (STAGES * STAGE_BYTES)         // 110592 (x2 CTA = 221KB)

#define CONV_BLOCKS  16384
#define DEQ_BLOCKS   11008

__device__ __align__(16) __half g_x16[(size_t)M_TOTAL * K_TOTAL];
__device__ __align__(16) __half g_w16[(size_t)N_TOTAL * K_TOTAL];

__device__ __forceinline__ uint32_t pack2(float a, float b) {
    __half2 h = __floats2half2_rn(a, b);
    return *reinterpret_cast<uint32_t*>(&h);
}

// ---------------------------------------------------------------------------
__global__ void k_prep(const float* __restrict__ x,
                       const int* __restrict__ q,
                       const float* __restrict__ scales,
                       const float* __restrict__ zeros) {
    if (blockIdx.x < CONV_BLOCKS) {
        unsigned idx = blockIdx.x * blockDim.x + threadIdx.x;
        size_t e = (size_t)idx * 8;
        const float4* src = reinterpret_cast<const float4*>(x + e);
        float4 a = src[0];
        float4 b = src[1];
        uint4 u;
        u.x = pack2(a.x, a.y);
        u.y = pack2(a.z, a.w);
        u.z = pack2(b.x, b.y);
        u.w = pack2(b.z, b.w);
        reinterpret_cast<uint4*>(g_x16)[idx] = u;
    } else {
        unsigned idx = (blockIdx.x - CONV_BLOCKS) * blockDim.x + threadIdx.x;
        unsigned o  = idx >> 8;
        unsigned k0 = (idx & 255u) * 16u;
        unsigned g  = k0 >> 7;
        float sc = scales[o * 32u + g];
        float zp = zeros [o * 32u + g];
        const int4* src = reinterpret_cast<const int4*>(q + (size_t)o * 4096 + k0);
        uint32_t outw[8];
#pragma unroll
        for (int w = 0; w < 4; w++) {
            int4 v = src[w];
            float f0 = ((float)v.x - zp) * sc;
            float f1 = ((float)v.y - zp) * sc;
            float f2 = ((float)v.z - zp) * sc;
            float f3 = ((float)v.w - zp) * sc;
            outw[w * 2]     = pack2(f0, f1);
            outw[w * 2 + 1] = pack2(f2, f3);
        }
        __half* dst = g_w16 + (size_t)o * 4096 + k0;
        reinterpret_cast<uint4*>(dst)[0] = make_uint4(outw[0], outw[1], outw[2], outw[3]);
        reinterpret_cast<uint4*>(dst)[1] = make_uint4(outw[4], outw[5], outw[6], outw[7]);
    }
}

// ---------------------------------------------------------------------------
__device__ __forceinline__ uint32_t smem_u32(const void* p) {
    return (uint32_t)__cvta_generic_to_shared(p);
}

__device__ __forceinline__ void cp_async16(uint32_t dst, const void* src) {
    asm volatile("cp.async.cg.shared.global [%0], [%1], 16;"
                 :: "r"(dst), "l"(src) : "memory");
}

__device__ __forceinline__ void ldmatrix_x4(uint32_t* r, uint32_t addr) {
    asm volatile("ldmatrix.sync.aligned.m8n8.x4.shared.b16 {%0,%1,%2,%3}, [%4];"
                 : "=r"(r[0]), "=r"(r[1]), "=r"(r[2]), "=r"(r[3]) : "r"(addr));
}

__device__ __forceinline__ void mma16816(float* c, const uint32_t* a,
                                         const uint32_t* b) {
    asm volatile(
        "mma.sync.aligned.m16n8k16.row.col.f32.f16.f16.f32 "
        "{%0,%1,%2,%3}, {%4,%5,%6,%7}, {%8,%9}, {%0,%1,%2,%3};"
        : "+f"(c[0]), "+f"(c[1]), "+f"(c[2]), "+f"(c[3])
        : "r"(a[0]), "r"(a[1]), "r"(a[2]), "r"(a[3]), "r"(b[0]), "r"(b[1]));
}

__device__ __forceinline__ void stg_cs_f2(float* p, float a, float b) {
    asm volatile("st.global.cs.v2.f32 [%0], {%1, %2};"
                 :: "l"(p), "f"(a), "f"(b) : "memory");
}

__global__ void __launch_bounds__(128, 2) k_gemm(float* __restrict__ out) {
    extern __shared__ __align__(16) unsigned char smem[];
    const uint32_t sbase = smem_u32(smem);
    const int tid  = threadIdx.x;
    const int lane = tid & 31;
    const int wid  = tid >> 5;
    const int wm   = wid >> 1;   // 0..1, 64 rows
    const int wn   = wid & 1;    // 0..1, 64 cols

    int pid   = blockIdx.x;
    int grp   = pid / (GROUP_M * N_TILES);
    int inpg  = pid % (GROUP_M * N_TILES);
    int pm    = grp * GROUP_M + (inpg % GROUP_M);
    int pn    = inpg / GROUP_M;
    const int mbase = pm * BM;
    const int nbase = pn * BN;

    const __half* gA = g_x16 + (size_t)mbase * K_TOTAL;
    const __half* gB = g_w16 + (size_t)nbase * K_TOTAL;

    const int ar = tid >> 3;          // 0..15
    const int ac = tid & 7;           // 16B chunk 0..7
    auto load_stage_A = [&](int s, int kt) {
        uint32_t dst = sbase + s * STAGE_BYTES;
        const __half* srcA = gA + kt * BK;
#pragma unroll
        for (int i = 0; i < 8; i++) {
            int r = ar + i * 16;
            cp_async16(dst + r * ROW_BYTES + ac * 16,
                       srcA + (size_t)r * K_TOTAL + ac * 8);
        }
    };
    auto load_stage_B = [&](int s, int kt) {
        uint32_t dst = sbase + s * STAGE_BYTES + A_TILE_BYTES;
        const __half* srcB = gB + kt * BK;
#pragma unroll
        for (int i = 0; i < 8; i++) {
            int r = ar + i * 16;
            cp_async16(dst + r * ROW_BYTES + ac * 16,
                       srcB + (size_t)r * K_TOTAL + ac * 8);
        }
    };

    float acc[4][8][4];
#pragma unroll
    for (int i = 0; i < 4; i++)
#pragma unroll
        for (int j = 0; j < 8; j++)
#pragma unroll
            for (int v = 0; v < 4; v++) acc[i][j][v] = 0.0f;

    const int a_row  = wm * 64 + (lane & 15);
    const int a_col8 = (lane >> 4);
    const int b_row  = wn * 64 + (lane & 7) + ((lane >> 4) << 3);
    const int b_col8 = ((lane >> 3) & 1);

    uint32_t afr[2][4][4];
    uint32_t bfr[2][8][2];

    auto ldsm_frags = [&](int buf, uint32_t Ab, uint32_t Bb, int koff) {
#pragma unroll
        for (int mi = 0; mi < 4; mi++)
            ldmatrix_x4(afr[buf][mi],
                        Ab + (a_row + mi * 16) * ROW_BYTES
                           + (koff + a_col8 * 8) * 2);
#pragma unroll
        for (int bi = 0; bi < 4; bi++) {
            uint32_t r[4];
            ldmatrix_x4(r, Bb + (b_row + bi * 16) * ROW_BYTES
                             + (koff + b_col8 * 8) * 2);
            bfr[buf][bi * 2][0]     = r[0];
            bfr[buf][bi * 2][1]     = r[1];
            bfr[buf][bi * 2 + 1][0] = r[2];
            bfr[buf][bi * 2 + 1][1] = r[3];
        }
    };
    auto mma_block = [&](int buf) {
#pragma unroll
        for (int mi = 0; mi < 4; mi++)
#pragma unroll
            for (int ni = 0; ni < 8; ni++)
                mma16816(acc[mi][ni], afr[buf][mi], bfr[buf][ni]);
    };

    // prologue: fill stages 0,1
    load_stage_A(0, 0);
    load_stage_B(0, 0);
    asm volatile("cp.async.commit_group;" ::: "memory");
    load_stage_A(1, 1);
    load_stage_B(1, 1);
    asm volatile("cp.async.commit_group;" ::: "memory");
    asm volatile("cp.async.wait_group 1;" ::: "memory");
    __syncthreads();

    // ks=0 frags of kt=0 into buffer 0
    ldsm_frags(0, sbase, sbase + A_TILE_BYTES, 0);

    int s = 0, sl = STAGES - 1;
    for (int kt = 0; kt < NKT; kt++) {
        uint32_t Ab = sbase + s * STAGE_BYTES;
        uint32_t Bb = Ab + A_TILE_BYTES;
        int snext = (s + 1 == STAGES) ? 0 : s + 1;
        uint32_t AbN = sbase + snext * STAGE_BYTES;
        uint32_t BbN = AbN + A_TILE_BYTES;
        const bool do_load = (kt + STAGES - 1 < NKT);

        // ks = 0
        ldsm_frags(1, Ab, Bb, 16);
        mma_block(0);
        if (do_load) load_stage_A(sl, kt + STAGES - 1);

        // ks = 1
        ldsm_frags(0, Ab, Bb, 32);
        mma_block(1);
        if (do_load) load_stage_B(sl, kt + STAGES - 1);
        asm volatile("cp.async.commit_group;" ::: "memory");

        // ks = 2
        ldsm_frags(1, Ab, Bb, 48);
        mma_block(0);

        // stage kt+1 is complete after this wait (only kt+2 pending)
        asm volatile("cp.async.wait_group %0;" :: "n"(STAGES - 2) : "memory");
        __syncthreads();

        // ks = 3: prefetch next kt's ks=0 frags from the resident next stage
        if (kt + 1 < NKT) ldsm_frags(0, AbN, BbN, 0);
        mma_block(1);

        s = snext;
        sl = (sl + 1 == STAGES) ? 0 : sl + 1;
    }

    const int erow = mbase + wm * 64 + (lane >> 2);
    const int ecol = nbase + wn * 64 + (lane & 3) * 2;
#pragma unroll
    for (int mi = 0; mi < 4; mi++) {
#pragma unroll
        for (int ni = 0; ni < 8; ni++) {
            int r0 = erow + mi * 16;
            int c  = ecol + ni * 8;
            stg_cs_f2(out + (size_t)r0 * N_TOTAL + c,
                      acc[mi][ni][0], acc[mi][ni][1]);
            stg_cs_f2(out + (size_t)(r0 + 8) * N_TOTAL + c,
                      acc[mi][ni][2], acc[mi][ni][3]);
        }
    }
}

// ---------------------------------------------------------------------------
extern "C" void kernel_launch(void* const* d_in, const int* in_sizes, int n_in,
                              void* d_out, int out_size) {
    (void)in_sizes; (void)n_in; (void)out_size;
    const float* x  = (const float*)d_in[0];
    const int*   qw = (const int*)d_in[1];
    const float* sc = (const float*)d_in[2];
    const float* zr = (const float*)d_in[3];
    float*       out = (float*)d_out;

    cudaFuncSetAttribute(k_gemm, cudaFuncAttributeMaxDynamicSharedMemorySize,
                         SMEM_BYTES);

    k_prep<<<CONV_BLOCKS + DEQ_BLOCKS, 256>>>(x, qw, sc, zr);
    k_gemm<<<M_TILES * N_TILES, 128, SMEM_BYTES>>>(out);   // 5504 CTAs
}